// round 2
// baseline (speedup 1.0000x reference)
#include <cuda_runtime.h>

// Scratch in device globals (no allocations allowed).
__device__ float g_G[8 * 256 * 256];        // Gram matrices G[b*4+q] : 256x256
__device__ float g_T[8 * 1024 * 256];       // Tstack[b*4+a] : 1024x256  (q-major rows)
__device__ float g_M[8 * 256 * 256];        // M[b*4+a] : 256x256

// ---------------------------------------------------------------------------
// 64x64 tile, 256 threads, 4x4 micro-tile per thread, BK=32.
// NN: C[m,n] += A[m,k] * B[k,n]   (A,B,C row-major)
// ---------------------------------------------------------------------------
__device__ __forceinline__ void gemm64_nn(
    const float* __restrict__ A, int lda,
    const float* __restrict__ B, int ldb,
    float* __restrict__ C, int ldc,
    int K, int m0, int n0)
{
    __shared__ float As[64][33];   // [m][k], padded (conflict-free col reads)
    __shared__ float Bs[32][64];   // [k][n], float4-readable

    const int tid = threadIdx.x;
    const int tx = tid & 15;       // 0..15 -> n sub-tile
    const int ty = tid >> 4;       // 0..15 -> m sub-tile
    const int kcA = tid & 31, mrA = tid >> 5;   // A loader: 8 m-rows/pass
    const int ncB = tid & 63, krB = tid >> 6;   // B loader: 4 k-rows/pass

    float acc[4][4] = {};

    for (int k0 = 0; k0 < K; k0 += 32) {
        #pragma unroll
        for (int p = 0; p < 8; p++)
            As[mrA + p * 8][kcA] = A[(size_t)(m0 + mrA + p * 8) * lda + (k0 + kcA)];
        #pragma unroll
        for (int p = 0; p < 8; p++)
            Bs[krB + p * 4][ncB] = B[(size_t)(k0 + krB + p * 4) * ldb + (n0 + ncB)];
        __syncthreads();

        #pragma unroll
        for (int kk = 0; kk < 32; kk++) {
            float a[4];
            #pragma unroll
            for (int i = 0; i < 4; i++) a[i] = As[ty * 4 + i][kk];
            float4 bv = *reinterpret_cast<const float4*>(&Bs[kk][tx * 4]);
            float b[4] = {bv.x, bv.y, bv.z, bv.w};
            #pragma unroll
            for (int i = 0; i < 4; i++)
                #pragma unroll
                for (int j = 0; j < 4; j++)
                    acc[i][j] = fmaf(a[i], b[j], acc[i][j]);
        }
        __syncthreads();
    }

    #pragma unroll
    for (int i = 0; i < 4; i++) {
        float4 v = make_float4(acc[i][0], acc[i][1], acc[i][2], acc[i][3]);
        *reinterpret_cast<float4*>(&C[(size_t)(m0 + ty * 4 + i) * ldc + n0 + tx * 4]) = v;
    }
}

// ---------------------------------------------------------------------------
// TN: C[m,n] += A[k,m] * B[k,n]   (A is [K x M] row-major -> C = A^T B)
// Used for the Gram matrix G = X^T X.
// ---------------------------------------------------------------------------
__device__ __forceinline__ void gemm64_tn(
    const float* __restrict__ A, int lda,
    const float* __restrict__ B, int ldb,
    float* __restrict__ C, int ldc,
    int K, int m0, int n0)
{
    __shared__ float As[32][64];   // [k][m]
    __shared__ float Bs[32][64];   // [k][n]

    const int tid = threadIdx.x;
    const int tx = tid & 15;
    const int ty = tid >> 4;
    const int mc = tid & 63, kr = tid >> 6;  // loaders: contiguous 64-wide rows

    float acc[4][4] = {};

    for (int k0 = 0; k0 < K; k0 += 32) {
        #pragma unroll
        for (int p = 0; p < 8; p++) {
            int k = k0 + kr + p * 4;
            As[kr + p * 4][mc] = A[(size_t)k * lda + m0 + mc];
            Bs[kr + p * 4][mc] = B[(size_t)k * ldb + n0 + mc];
        }
        __syncthreads();

        #pragma unroll
        for (int kk = 0; kk < 32; kk++) {
            float4 av = *reinterpret_cast<const float4*>(&As[kk][ty * 4]);
            float4 bv = *reinterpret_cast<const float4*>(&Bs[kk][tx * 4]);
            float a[4] = {av.x, av.y, av.z, av.w};
            float b[4] = {bv.x, bv.y, bv.z, bv.w};
            #pragma unroll
            for (int i = 0; i < 4; i++)
                #pragma unroll
                for (int j = 0; j < 4; j++)
                    acc[i][j] = fmaf(a[i], b[j], acc[i][j]);
        }
        __syncthreads();
    }

    #pragma unroll
    for (int i = 0; i < 4; i++) {
        float4 v = make_float4(acc[i][0], acc[i][1], acc[i][2], acc[i][3]);
        *reinterpret_cast<float4*>(&C[(size_t)(m0 + ty * 4 + i) * ldc + n0 + tx * 4]) = v;
    }
}

// ---------------------------------------------------------------------------
// Stage A: G[b,q] = X_{b,q}^T X_{b,q},  X_{b,q} = hidden[b, :, q*256:(q+1)*256]
// grid (16, 8): 16 tiles of 256x256, 8 (b,q) pairs
// ---------------------------------------------------------------------------
__global__ void __launch_bounds__(256) k_gram(const float* __restrict__ hidden)
{
    const int pair = blockIdx.y;                 // b*4 + q
    const int b = pair >> 2, q = pair & 3;
    const float* X = hidden + (size_t)b * 2048 * 1024 + q * 256;
    float* C = g_G + (size_t)pair * 65536;
    const int m0 = (blockIdx.x >> 2) * 64, n0 = (blockIdx.x & 3) * 64;
    gemm64_tn(X, 1024, X, 1024, C, 256, 2048, m0, n0);
}

// ---------------------------------------------------------------------------
// Stage B1: Tstack[b,a][q*256+f, g'] = (G[b,q] @ C_{a,q})[f, g']
// grid (16, 32)
// ---------------------------------------------------------------------------
__global__ void __launch_bounds__(256) k_gc(const float* __restrict__ comb)
{
    const int combo = blockIdx.y;                // ((b*4+a)*4 + q)
    const int q = combo & 3, a = (combo >> 2) & 3, b = combo >> 4;
    const float* A = g_G + (size_t)(b * 4 + q) * 65536;
    const float* B = comb + ((size_t)a * 1024 + q * 256) * 256;
    float* C = g_T + ((size_t)(b * 4 + a) * 1024 + q * 256) * 256;
    const int m0 = (blockIdx.x >> 2) * 64, n0 = (blockIdx.x & 3) * 64;
    gemm64_nn(A, 256, B, 256, C, 256, 256, m0, n0);
}

// ---------------------------------------------------------------------------
// Stage B2: M[b,a] = queries[a] (256x1024) @ Tstack[b,a] (1024x256)
// grid (16, 8)
// ---------------------------------------------------------------------------
__global__ void __launch_bounds__(256) k_fold(const float* __restrict__ queries)
{
    const int combo = blockIdx.y;                // b*4 + a
    const int a = combo & 3;
    const float* A = queries + (size_t)a * 256 * 1024;
    const float* B = g_T + (size_t)combo * 1024 * 256;
    float* C = g_M + (size_t)combo * 65536;
    const int m0 = (blockIdx.x >> 2) * 64, n0 = (blockIdx.x & 3) * 64;
    gemm64_nn(A, 1024, B, 256, C, 256, 1024, m0, n0);
}

// ---------------------------------------------------------------------------
// Stage C: out[b, :, a*256:(a+1)*256] = hidden[b, :, a*256:(a+1)*256] @ M[b,a]
// grid (128, 8): 32x4 tiles of 2048x256, 8 (b,a) pairs
// ---------------------------------------------------------------------------
__global__ void __launch_bounds__(256) k_out(const float* __restrict__ hidden,
                                             float* __restrict__ out)
{
    const int combo = blockIdx.y;                // b*4 + a
    const int b = combo >> 2, a = combo & 3;
    const float* A = hidden + (size_t)b * 2048 * 1024 + a * 256;
    const float* B = g_M + (size_t)combo * 65536;
    float* C = out + (size_t)b * 2048 * 1024 + a * 256;
    const int m0 = (blockIdx.x >> 2) * 64, n0 = (blockIdx.x & 3) * 64;
    gemm64_nn(A, 1024, B, 256, C, 1024, 256, m0, n0);
}

extern "C" void kernel_launch(void* const* d_in, const int* in_sizes, int n_in,
                              void* d_out, int out_size)
{
    const float* hidden   = (const float*)d_in[0];   // [2, 2048, 1024]
    const float* queries  = (const float*)d_in[1];   // [4, 256, 1024]
    const float* comb     = (const float*)d_in[2];   // [4, 1024, 256]
    float* out = (float*)d_out;                      // [2, 2048, 1024]

    dim3 blk(256);
    k_gram<<<dim3(16, 8),  blk>>>(hidden);
    k_gc  <<<dim3(16, 32), blk>>>(comb);
    k_fold<<<dim3(16, 8),  blk>>>(queries);
    k_out <<<dim3(128, 8), blk>>>(hidden, out);
}